// round 3
// baseline (speedup 1.0000x reference)
#include <cuda_runtime.h>

typedef unsigned long long ull;

// ---------------- dimensions ----------------
static constexpr int DA = 45, DB = 102;

// ---------------- shared layout (floats; every offset & row stride multiple of 4 floats = 16B) ----
static constexpr int OFF_WaH = 0;                    // 45 x 36  (tower-a outputs 0..35)
static constexpr int OFF_WaL = 1620;                 // 45 x 32  (outputs 36..67)
static constexpr int OFF_baH = 3060;                 // 36
static constexpr int OFF_baL = 3096;                 // 32
static constexpr int OFF_WbH = 3128;                 // 102 x 36
static constexpr int OFF_WbL = 6800;                 // 102 x 32
static constexpr int OFF_bbH = 10064;                // 36
static constexpr int OFF_bbL = 10100;                // 32
static constexpr int OFF_W0  = 10132;                // 140 x 36 (pad from 34)
static constexpr int OFF_B0  = 15172;                // 36
static constexpr int OFF_W1  = 15208;                // 34 x 36  (pad from 34x34)
static constexpr int OFF_B1  = 16432;                // 36
static constexpr int OFF_W2  = 16468;                // 34 x 20
static constexpr int OFF_B2  = 17148;                // 20
static constexpr int OFF_W3  = 17168;                // 20 x 20
static constexpr int OFF_B3  = 17568;
static constexpr int OFF_W4  = 17588;
static constexpr int OFF_B4  = 17988;
static constexpr int OFF_W5  = 18008;
static constexpr int OFF_B5  = 18408;
static constexpr int OFF_W6  = 18428;
static constexpr int OFF_B6  = 18828;
static constexpr int OFF_W7  = 18848;                // 20 x 8 (pad from 20x5)
static constexpr int OFF_B7  = 19008;                // 8
static constexpr int OFF_W8  = 19016;                // 5 x 4 (pad from 5x2)
static constexpr int OFF_B8  = 19036;                // 4
static constexpr int OFF_W9  = 19040;                // [w9_0, w9_1, b9, 0]
static constexpr int OFF_STAGE = 19044;              // 6 warps x 35 x 32
static constexpr int STAGE_STRIDE = 35;              // odd -> conflict-free per-lane rows
static constexpr int STAGE_WARP = STAGE_STRIDE * 32; // 1120
static constexpr int SMEM_FLOATS = OFF_STAGE + 6 * STAGE_WARP;  // 25764
static constexpr int SMEM_BYTES  = SMEM_FLOATS * 4;             // 103056

// ---------------- f32x2 helpers ----------------
__device__ __forceinline__ ull pack2(float x, float y) {
    ull r; asm("mov.b64 %0, {%1, %2};" : "=l"(r) : "f"(x), "f"(y)); return r;
}
__device__ __forceinline__ void unpack2(ull v, float& x, float& y) {
    asm("mov.b64 {%0, %1}, %2;" : "=f"(x), "=f"(y) : "l"(v));
}
__device__ __forceinline__ ull ffma2(ull a, ull b, ull c) {
    ull d; asm("fma.rn.f32x2 %0, %1, %2, %3;" : "=l"(d) : "l"(a), "l"(b), "l"(c)); return d;
}
__device__ __forceinline__ float lrelu(float x) { return fmaxf(x, 0.01f * x); }

// rank-1 update of N2 f32x2 accumulators from a 16B-aligned weight row (LDS.128 pairs)
template <int N2>
__device__ __forceinline__ void step(ull (&acc)[N2], const float* __restrict__ wrow, ull xs) {
#pragma unroll
    for (int p = 0; p < N2 / 2; p++) {
        ulonglong2 w = *reinterpret_cast<const ulonglong2*>(wrow + 4 * p);
        acc[2 * p + 0] = ffma2(xs, w.x, acc[2 * p + 0]);
        acc[2 * p + 1] = ffma2(xs, w.y, acc[2 * p + 1]);
    }
}
template <int N2>
__device__ __forceinline__ void initb(ull (&acc)[N2], const float* __restrict__ bsrc) {
#pragma unroll
    for (int p = 0; p < N2 / 2; p++) {
        ulonglong2 w = *reinterpret_cast<const ulonglong2*>(bsrc + 4 * p);
        acc[2 * p + 0] = w.x;
        acc[2 * p + 1] = w.y;
    }
}

// feed one concat activation (index k in [0,140)) into the 36-wide layer-0 accumulator
__device__ __forceinline__ void feed0(float v, int k, const float* __restrict__ sm, ull (&acc0)[18]) {
    ull xs = pack2(v, v);
    step<18>(acc0, sm + OFF_W0 + k * 36, xs);
}

// one K-chunk of a tower: coalesced warp staging of x, then accumulation into both output halves
template <int C, int K>
__device__ __forceinline__ void tower_chunk(const float* __restrict__ gwarp, int lane,
                                            float* __restrict__ stg, const float* __restrict__ sm,
                                            int wH, int wL, int k0,
                                            ull (&accH)[18], ull (&accL)[16]) {
    __syncwarp();
    for (int i = lane; i < 32 * C; i += 32) {
        int r = i / C, c = i - r * C;
        stg[r * STAGE_STRIDE + c] = gwarp[(size_t)r * K + (k0 + c)];
    }
    __syncwarp();
    const float* xrow = stg + lane * STAGE_STRIDE;
#pragma unroll 2
    for (int k = 0; k < C; k++) {
        float xk = xrow[k];
        ull xs = pack2(xk, xk);
        step<18>(accH, sm + wH + (k0 + k) * 36, xs);
        step<16>(accL, sm + wL + (k0 + k) * 32, xs);
    }
}

// dense layer, register input, output dim = 2*N2 (padded even), weight row stride = 2*N2 floats
template <int K, int N2, int IN>
__device__ __forceinline__ void dense(const float (&in)[IN], float (&out)[2 * N2],
                                      const float* __restrict__ sm, int woff, int boff) {
    static_assert(IN >= K, "bad dims");
    ull acc[N2];
    initb<N2>(acc, sm + boff);
#pragma unroll 2
    for (int k = 0; k < K; k++) {
        ull xs = pack2(in[k], in[k]);
        step<N2>(acc, sm + woff + k * (2 * N2), xs);
    }
#pragma unroll
    for (int p = 0; p < N2; p++) {
        float v0, v1; unpack2(acc[p], v0, v1);
        out[2 * p + 0] = lrelu(v0);
        out[2 * p + 1] = lrelu(v1);
    }
}

__global__ __launch_bounds__(192, 2)
void Net_67954972557347_kernel(
    const float* __restrict__ a, const float* __restrict__ b, const float* __restrict__ meta,
    const float* __restrict__ Wa, const float* __restrict__ ba,
    const float* __restrict__ Wb, const float* __restrict__ bb,
    const float* __restrict__ W0, const float* __restrict__ B0,
    const float* __restrict__ W1, const float* __restrict__ B1,
    const float* __restrict__ W2, const float* __restrict__ B2,
    const float* __restrict__ W3, const float* __restrict__ B3,
    const float* __restrict__ W4, const float* __restrict__ B4,
    const float* __restrict__ W5, const float* __restrict__ B5,
    const float* __restrict__ W6, const float* __restrict__ B6,
    const float* __restrict__ W7, const float* __restrict__ B7,
    const float* __restrict__ W8, const float* __restrict__ B8,
    const float* __restrict__ W9, const float* __restrict__ B9,
    float* __restrict__ outp, int nrows)
{
    extern __shared__ float sm[];
    const int tid = threadIdx.x, nt = blockDim.x;
    const int lane = tid & 31, warp = tid >> 5;

    // ---- stage weights into shared with 16B-aligned padded layout ----
    for (int i = tid; i < 45 * 36; i += nt) { int r = i / 36, c = i - r * 36; sm[OFF_WaH + i] = Wa[r * 68 + c]; }
    for (int i = tid; i < 45 * 32; i += nt) { int r = i / 32, c = i - r * 32; sm[OFF_WaL + i] = Wa[r * 68 + 36 + c]; }
    for (int i = tid; i < 36; i += nt) sm[OFF_baH + i] = ba[i];
    for (int i = tid; i < 32; i += nt) sm[OFF_baL + i] = ba[36 + i];
    for (int i = tid; i < 102 * 36; i += nt) { int r = i / 36, c = i - r * 36; sm[OFF_WbH + i] = Wb[r * 68 + c]; }
    for (int i = tid; i < 102 * 32; i += nt) { int r = i / 32, c = i - r * 32; sm[OFF_WbL + i] = Wb[r * 68 + 36 + c]; }
    for (int i = tid; i < 36; i += nt) sm[OFF_bbH + i] = bb[i];
    for (int i = tid; i < 32; i += nt) sm[OFF_bbL + i] = bb[36 + i];
    for (int i = tid; i < 140 * 36; i += nt) { int r = i / 36, c = i - r * 36; sm[OFF_W0 + i] = (c < 34) ? W0[r * 34 + c] : 0.0f; }
    for (int i = tid; i < 36; i += nt) sm[OFF_B0 + i] = (i < 34) ? B0[i] : 0.0f;
    for (int i = tid; i < 34 * 36; i += nt) { int r = i / 36, c = i - r * 36; sm[OFF_W1 + i] = (c < 34) ? W1[r * 34 + c] : 0.0f; }
    for (int i = tid; i < 36; i += nt) sm[OFF_B1 + i] = (i < 34) ? B1[i] : 0.0f;
    for (int i = tid; i < 34 * 20; i += nt) sm[OFF_W2 + i] = W2[i];
    for (int i = tid; i < 20; i += nt) sm[OFF_B2 + i] = B2[i];
    for (int i = tid; i < 400; i += nt) sm[OFF_W3 + i] = W3[i];
    for (int i = tid; i < 20; i += nt) sm[OFF_B3 + i] = B3[i];
    for (int i = tid; i < 400; i += nt) sm[OFF_W4 + i] = W4[i];
    for (int i = tid; i < 20; i += nt) sm[OFF_B4 + i] = B4[i];
    for (int i = tid; i < 400; i += nt) sm[OFF_W5 + i] = W5[i];
    for (int i = tid; i < 20; i += nt) sm[OFF_B5 + i] = B5[i];
    for (int i = tid; i < 400; i += nt) sm[OFF_W6 + i] = W6[i];
    for (int i = tid; i < 20; i += nt) sm[OFF_B6 + i] = B6[i];
    for (int i = tid; i < 20 * 8; i += nt) { int r = i / 8, c = i - r * 8; sm[OFF_W7 + i] = (c < 5) ? W7[r * 5 + c] : 0.0f; }
    for (int i = tid; i < 8; i += nt) sm[OFF_B7 + i] = (i < 5) ? B7[i] : 0.0f;
    for (int i = tid; i < 5 * 4; i += nt) { int r = i / 4, c = i - r * 4; sm[OFF_W8 + i] = (c < 2) ? W8[r * 2 + c] : 0.0f; }
    for (int i = tid; i < 4; i += nt) sm[OFF_B8 + i] = (i < 2) ? B8[i] : 0.0f;
    if (tid == 0) { sm[OFF_W9 + 0] = W9[0]; sm[OFF_W9 + 1] = W9[1]; sm[OFF_W9 + 2] = B9[0]; sm[OFF_W9 + 3] = 0.0f; }
    __syncthreads();

    float* stg = sm + OFF_STAGE + warp * STAGE_WARP;
    const int stride = gridDim.x * blockDim.x;

    for (int row = blockIdx.x * blockDim.x + tid; row < nrows; row += stride) {
        const int wrow0 = row - lane;  // warp-uniform base row (nrows % 32 == 0)

        ull acc0[18];
        initb<18>(acc0, sm + OFF_B0);

        {   // tower a -> concat[0..67]
            ull accH[18], accL[16];
            initb<18>(accH, sm + OFF_baH);
            initb<16>(accL, sm + OFF_baL);
            const float* ga = a + (size_t)wrow0 * DA;
            tower_chunk<34, DA>(ga, lane, stg, sm, OFF_WaH, OFF_WaL, 0, accH, accL);
            tower_chunk<11, DA>(ga, lane, stg, sm, OFF_WaH, OFF_WaL, 34, accH, accL);
#pragma unroll
            for (int p = 0; p < 18; p++) {
                float v0, v1; unpack2(accH[p], v0, v1);
                feed0(lrelu(v0), 2 * p + 0, sm, acc0);
                feed0(lrelu(v1), 2 * p + 1, sm, acc0);
            }
#pragma unroll
            for (int p = 0; p < 16; p++) {
                float v0, v1; unpack2(accL[p], v0, v1);
                feed0(lrelu(v0), 36 + 2 * p + 0, sm, acc0);
                feed0(lrelu(v1), 36 + 2 * p + 1, sm, acc0);
            }
            // tower b -> concat[68..135]
            initb<18>(accH, sm + OFF_bbH);
            initb<16>(accL, sm + OFF_bbL);
            const float* gb = b + (size_t)wrow0 * DB;
            tower_chunk<34, DB>(gb, lane, stg, sm, OFF_WbH, OFF_WbL, 0,  accH, accL);
            tower_chunk<34, DB>(gb, lane, stg, sm, OFF_WbH, OFF_WbL, 34, accH, accL);
            tower_chunk<34, DB>(gb, lane, stg, sm, OFF_WbH, OFF_WbL, 68, accH, accL);
#pragma unroll
            for (int p = 0; p < 18; p++) {
                float v0, v1; unpack2(accH[p], v0, v1);
                feed0(lrelu(v0), 68 + 2 * p + 0, sm, acc0);
                feed0(lrelu(v1), 68 + 2 * p + 1, sm, acc0);
            }
#pragma unroll
            for (int p = 0; p < 16; p++) {
                float v0, v1; unpack2(accL[p], v0, v1);
                feed0(lrelu(v0), 104 + 2 * p + 0, sm, acc0);
                feed0(lrelu(v1), 104 + 2 * p + 1, sm, acc0);
            }
        }

        // meta -> concat[136..139] (no activation on meta in the reference)
        {
            float4 m = *reinterpret_cast<const float4*>(meta + (size_t)row * 4);
            feed0(m.x, 136, sm, acc0);
            feed0(m.y, 137, sm, acc0);
            feed0(m.z, 138, sm, acc0);
            feed0(m.w, 139, sm, acc0);
        }

        float c1[36];
#pragma unroll
        for (int p = 0; p < 18; p++) {
            float v0, v1; unpack2(acc0[p], v0, v1);
            c1[2 * p + 0] = lrelu(v0);
            c1[2 * p + 1] = lrelu(v1);
        }

        float c2[36]; dense<34, 18>(c1, c2, sm, OFF_W1, OFF_B1);
        float c3[20]; dense<34, 10>(c2, c3, sm, OFF_W2, OFF_B2);
        float c4[20]; dense<20, 10>(c3, c4, sm, OFF_W3, OFF_B3);
        float c5[20]; dense<20, 10>(c4, c5, sm, OFF_W4, OFF_B4);
        float c6[20]; dense<20, 10>(c5, c6, sm, OFF_W5, OFF_B5);
        float c7[20]; dense<20, 10>(c6, c7, sm, OFF_W6, OFF_B6);
        float c8[8];  dense<20, 4>(c7, c8, sm, OFF_W7, OFF_B7);   // real 5, pad lanes = 0
        float c9[4];  dense<5, 2>(c8, c9, sm, OFF_W8, OFF_B8);    // real 2

        float o = fmaf(c9[0], sm[OFF_W9 + 0], fmaf(c9[1], sm[OFF_W9 + 1], sm[OFF_W9 + 2]));
        outp[row] = lrelu(o);
    }
}

extern "C" void kernel_launch(void* const* d_in, const int* in_sizes, int n_in,
                              void* d_out, int out_size) {
    const float* a    = (const float*)d_in[0];
    const float* b    = (const float*)d_in[1];
    const float* meta = (const float*)d_in[2];
    const float* Wa   = (const float*)d_in[3];
    const float* ba   = (const float*)d_in[4];
    const float* Wb   = (const float*)d_in[5];
    const float* bb   = (const float*)d_in[6];
    const float* W[10], *Bb[10];
    for (int i = 0; i < 10; i++) {
        W[i]  = (const float*)d_in[7 + 2 * i];
        Bb[i] = (const float*)d_in[8 + 2 * i];
    }
    float* outp = (float*)d_out;
    const int nrows = in_sizes[0] / DA;

    cudaFuncSetAttribute(Net_67954972557347_kernel,
                         cudaFuncAttributeMaxDynamicSharedMemorySize, SMEM_BYTES);

    // 2 blocks/SM x 148 SMs, 192 threads (12 warps/SM target)
    Net_67954972557347_kernel<<<296, 192, SMEM_BYTES>>>(
        a, b, meta, Wa, ba, Wb, bb,
        W[0], Bb[0], W[1], Bb[1], W[2], Bb[2], W[3], Bb[3], W[4], Bb[4],
        W[5], Bb[5], W[6], Bb[6], W[7], Bb[7], W[8], Bb[8], W[9], Bb[9],
        outp, nrows);
}

// round 4
// speedup vs baseline: 1.1455x; 1.1455x over previous
#include <cuda_runtime.h>

typedef unsigned long long ull;

// ---------------- dimensions ----------------
static constexpr int DA = 45, DB = 102;

// ---------------- shared layout (floats). All weight rows are 16B-aligned:
// 68-wide (272B), 36-wide (144B), 20-wide (80B), 8-wide (32B), 4-wide (16B).
static constexpr int OFF_Wa = 0;        // 45 x 68
static constexpr int OFF_ba = 3060;     // 68
static constexpr int OFF_Wb = 3128;     // 102 x 68
static constexpr int OFF_bb = 10064;    // 68
static constexpr int OFF_W0 = 10132;    // 140 x 36 (padded from 34)
static constexpr int OFF_B0 = 15172;    // 36
static constexpr int OFF_W1 = 15208;    // 34 x 36 (padded)
static constexpr int OFF_B1 = 16432;    // 36
static constexpr int OFF_W2 = 16468;    // 34 x 20
static constexpr int OFF_B2 = 17148;    // 20
static constexpr int OFF_W3 = 17168;    static constexpr int OFF_B3 = 17568;
static constexpr int OFF_W4 = 17588;    static constexpr int OFF_B4 = 17988;
static constexpr int OFF_W5 = 18008;    static constexpr int OFF_B5 = 18408;
static constexpr int OFF_W6 = 18428;    static constexpr int OFF_B6 = 18828;
static constexpr int OFF_W7 = 18848;    // 20 x 8 (padded from 20x5)
static constexpr int OFF_B7 = 19008;    // 8
static constexpr int OFF_W8 = 19016;    // 5 x 4 (padded from 5x2)
static constexpr int OFF_B8 = 19036;    // 4
static constexpr int OFF_W9 = 19040;    // [w9_0, w9_1, b9, 0]
static constexpr int OFF_STAGE = 19044; // 8 warps x 64 rows x stride 33
static constexpr int STG_STRIDE = 33;   // odd -> conflict-free STS and row reads
static constexpr int STG_WARP = 64 * STG_STRIDE;                 // 2112
static constexpr int SMEM_FLOATS = OFF_STAGE + 8 * STG_WARP;     // 35940
static constexpr int SMEM_BYTES = SMEM_FLOATS * 4;               // 143760

// ---------------- f32x2 helpers ----------------
__device__ __forceinline__ ull pack2(float x, float y) {
    ull r; asm("mov.b64 %0, {%1, %2};" : "=l"(r) : "f"(x), "f"(y)); return r;
}
__device__ __forceinline__ void unpack2(ull v, float& x, float& y) {
    asm("mov.b64 {%0, %1}, %2;" : "=f"(x), "=f"(y) : "l"(v));
}
__device__ __forceinline__ ull ffma2(ull a, ull b, ull c) {
    ull d; asm("fma.rn.f32x2 %0, %1, %2, %3;" : "=l"(d) : "l"(a), "l"(b), "l"(c)); return d;
}
__device__ __forceinline__ float lrelu(float x) { return fmaxf(x, 0.01f * x); }

// acc layout convention for a weight ulonglong2 p (covering output cols 4p..4p+3):
//   acc[4p+0] = rowA cols(4p,4p+1)   acc[4p+1] = rowB cols(4p,4p+1)
//   acc[4p+2] = rowA cols(4p+2,4p+3) acc[4p+3] = rowB cols(4p+2,4p+3)
template <int NW>
__device__ __forceinline__ void init_pair(ull* acc, const float* __restrict__ bsrc) {
#pragma unroll
    for (int p = 0; p < NW; p++) {
        ulonglong2 w = *reinterpret_cast<const ulonglong2*>(bsrc + 4 * p);
        acc[4 * p + 0] = w.x; acc[4 * p + 1] = w.x;
        acc[4 * p + 2] = w.y; acc[4 * p + 3] = w.y;
    }
}

// Stage chunk [k0, k0+cv) of 64 rows (row-major, stride 33). Coalesced LDG, conflict-free STS.
template <int K>
__device__ __forceinline__ void stage_chunk(const float* __restrict__ gw, int k0, int cv,
                                            float* __restrict__ stg, int lane) {
    __syncwarp();
    if (lane < cv) {
        const float* g = gw + k0 + lane;
        float* s = stg + lane;
#pragma unroll 8
        for (int r = 0; r < 64; r++) s[r * STG_STRIDE] = g[r * K];
    }
    __syncwarp();
}

// One tower half: K-wide GEMV into 4*NW f32x2 accumulators (2 rows x 2*NW col-pairs).
// Weights LDS.128, reused across both rows (4 FFMA2 per load).
template <int K, int NW>
__device__ __forceinline__ void tower_pass(const float* __restrict__ gw,
                                           const float* __restrict__ sm, int woff, int hoff,
                                           float* __restrict__ stg, int lane, ull* acc) {
    for (int k0 = 0; k0 < K; k0 += 32) {
        int cv = K - k0; if (cv > 32) cv = 32;
        stage_chunk<K>(gw, k0, cv, stg, lane);
        const float* x0p = stg + lane * STG_STRIDE;            // row A = lane
        const float* x1p = stg + (lane + 32) * STG_STRIDE;     // row B = lane+32
#pragma unroll 4
        for (int k = 0; k < cv; k++) {
            float x0 = x0p[k], x1 = x1p[k];
            ull xs0 = pack2(x0, x0), xs1 = pack2(x1, x1);
            const ulonglong2* wr =
                reinterpret_cast<const ulonglong2*>(sm + woff + (k0 + k) * 68 + hoff);
#pragma unroll
            for (int p = 0; p < NW; p++) {
                ulonglong2 w = wr[p];
                acc[4 * p + 0] = ffma2(xs0, w.x, acc[4 * p + 0]);
                acc[4 * p + 1] = ffma2(xs1, w.x, acc[4 * p + 1]);
                acc[4 * p + 2] = ffma2(xs0, w.y, acc[4 * p + 2]);
                acc[4 * p + 3] = ffma2(xs1, w.y, acc[4 * p + 3]);
            }
        }
    }
}

// Feed one concat index (both rows) into the 36-wide layer-0 accumulator.
__device__ __forceinline__ void feed0_pair(float va, float vb, int kidx,
                                           const float* __restrict__ sm, ull* acc0) {
    ull xs0 = pack2(va, va), xs1 = pack2(vb, vb);
    const ulonglong2* wr = reinterpret_cast<const ulonglong2*>(sm + OFF_W0 + kidx * 36);
#pragma unroll
    for (int p = 0; p < 9; p++) {
        ulonglong2 w = wr[p];
        acc0[4 * p + 0] = ffma2(xs0, w.x, acc0[4 * p + 0]);
        acc0[4 * p + 1] = ffma2(xs1, w.x, acc0[4 * p + 1]);
        acc0[4 * p + 2] = ffma2(xs0, w.y, acc0[4 * p + 2]);
        acc0[4 * p + 3] = ffma2(xs1, w.y, acc0[4 * p + 3]);
    }
}

// LeakyReLU tower-half outputs and feed them into acc0 at concat offset cbase.
template <int NW>
__device__ __forceinline__ void feed_tower(const ull* acc, int cbase,
                                           const float* __restrict__ sm, ull* acc0) {
#pragma unroll
    for (int p = 0; p < NW; p++) {
        float a0, a1, b0, b1;
        unpack2(acc[4 * p + 0], a0, a1);
        unpack2(acc[4 * p + 1], b0, b1);
        feed0_pair(lrelu(a0), lrelu(b0), cbase + 4 * p + 0, sm, acc0);
        feed0_pair(lrelu(a1), lrelu(b1), cbase + 4 * p + 1, sm, acc0);
        unpack2(acc[4 * p + 2], a0, a1);
        unpack2(acc[4 * p + 3], b0, b1);
        feed0_pair(lrelu(a0), lrelu(b0), cbase + 4 * p + 2, sm, acc0);
        feed0_pair(lrelu(a1), lrelu(b1), cbase + 4 * p + 3, sm, acc0);
    }
}

// Dense layer for both rows; NP = padded output dim (multiple of 4).
template <int K, int NP, int INN>
__device__ __forceinline__ void dense_pair(const float (&inA)[INN], const float (&inB)[INN],
                                           float (&outA)[NP], float (&outB)[NP],
                                           const float* __restrict__ sm, int woff, int boff) {
    static_assert(INN >= K && NP % 4 == 0, "bad dims");
    constexpr int NW = NP / 4;
    ull acc[4 * NW];
    init_pair<NW>(acc, sm + boff);
#pragma unroll
    for (int k = 0; k < K; k++) {
        ull xs0 = pack2(inA[k], inA[k]), xs1 = pack2(inB[k], inB[k]);
        const ulonglong2* wr = reinterpret_cast<const ulonglong2*>(sm + woff + k * NP);
#pragma unroll
        for (int p = 0; p < NW; p++) {
            ulonglong2 w = wr[p];
            acc[4 * p + 0] = ffma2(xs0, w.x, acc[4 * p + 0]);
            acc[4 * p + 1] = ffma2(xs1, w.x, acc[4 * p + 1]);
            acc[4 * p + 2] = ffma2(xs0, w.y, acc[4 * p + 2]);
            acc[4 * p + 3] = ffma2(xs1, w.y, acc[4 * p + 3]);
        }
    }
#pragma unroll
    for (int p = 0; p < NW; p++) {
        float v0, v1;
        unpack2(acc[4 * p + 0], v0, v1); outA[4 * p + 0] = lrelu(v0); outA[4 * p + 1] = lrelu(v1);
        unpack2(acc[4 * p + 1], v0, v1); outB[4 * p + 0] = lrelu(v0); outB[4 * p + 1] = lrelu(v1);
        unpack2(acc[4 * p + 2], v0, v1); outA[4 * p + 2] = lrelu(v0); outA[4 * p + 3] = lrelu(v1);
        unpack2(acc[4 * p + 3], v0, v1); outB[4 * p + 2] = lrelu(v0); outB[4 * p + 3] = lrelu(v1);
    }
}

__global__ __launch_bounds__(256, 1)
void Net_67954972557347_kernel(
    const float* __restrict__ a, const float* __restrict__ b, const float* __restrict__ meta,
    const float* __restrict__ Wa, const float* __restrict__ ba,
    const float* __restrict__ Wb, const float* __restrict__ bb,
    const float* __restrict__ W0, const float* __restrict__ B0,
    const float* __restrict__ W1, const float* __restrict__ B1,
    const float* __restrict__ W2, const float* __restrict__ B2,
    const float* __restrict__ W3, const float* __restrict__ B3,
    const float* __restrict__ W4, const float* __restrict__ B4,
    const float* __restrict__ W5, const float* __restrict__ B5,
    const float* __restrict__ W6, const float* __restrict__ B6,
    const float* __restrict__ W7, const float* __restrict__ B7,
    const float* __restrict__ W8, const float* __restrict__ B8,
    const float* __restrict__ W9, const float* __restrict__ B9,
    float* __restrict__ outp, int nrows)
{
    extern __shared__ float sm[];
    const int tid = threadIdx.x, nt = blockDim.x;
    const int lane = tid & 31, warp = tid >> 5;

    // ---- stage weights (one-time; div-by-const only here) ----
    for (int i = tid; i < 45 * 68; i += nt) sm[OFF_Wa + i] = Wa[i];
    for (int i = tid; i < 68; i += nt) sm[OFF_ba + i] = ba[i];
    for (int i = tid; i < 102 * 68; i += nt) sm[OFF_Wb + i] = Wb[i];
    for (int i = tid; i < 68; i += nt) sm[OFF_bb + i] = bb[i];
    for (int i = tid; i < 140 * 36; i += nt) { int r = i / 36, c = i - r * 36; sm[OFF_W0 + i] = (c < 34) ? W0[r * 34 + c] : 0.0f; }
    for (int i = tid; i < 36; i += nt) sm[OFF_B0 + i] = (i < 34) ? B0[i] : 0.0f;
    for (int i = tid; i < 34 * 36; i += nt) { int r = i / 36, c = i - r * 36; sm[OFF_W1 + i] = (c < 34) ? W1[r * 34 + c] : 0.0f; }
    for (int i = tid; i < 36; i += nt) sm[OFF_B1 + i] = (i < 34) ? B1[i] : 0.0f;
    for (int i = tid; i < 34 * 20; i += nt) sm[OFF_W2 + i] = W2[i];
    for (int i = tid; i < 20; i += nt) sm[OFF_B2 + i] = B2[i];
    for (int i = tid; i < 400; i += nt) sm[OFF_W3 + i] = W3[i];
    for (int i = tid; i < 20; i += nt) sm[OFF_B3 + i] = B3[i];
    for (int i = tid; i < 400; i += nt) sm[OFF_W4 + i] = W4[i];
    for (int i = tid; i < 20; i += nt) sm[OFF_B4 + i] = B4[i];
    for (int i = tid; i < 400; i += nt) sm[OFF_W5 + i] = W5[i];
    for (int i = tid; i < 20; i += nt) sm[OFF_B5 + i] = B5[i];
    for (int i = tid; i < 400; i += nt) sm[OFF_W6 + i] = W6[i];
    for (int i = tid; i < 20; i += nt) sm[OFF_B6 + i] = B6[i];
    for (int i = tid; i < 20 * 8; i += nt) { int r = i >> 3, c = i & 7; sm[OFF_W7 + i] = (c < 5) ? W7[r * 5 + c] : 0.0f; }
    for (int i = tid; i < 8; i += nt) sm[OFF_B7 + i] = (i < 5) ? B7[i] : 0.0f;
    for (int i = tid; i < 5 * 4; i += nt) { int r = i >> 2, c = i & 3; sm[OFF_W8 + i] = (c < 2) ? W8[r * 2 + c] : 0.0f; }
    for (int i = tid; i < 4; i += nt) sm[OFF_B8 + i] = (i < 2) ? B8[i] : 0.0f;
    if (tid == 0) { sm[OFF_W9 + 0] = W9[0]; sm[OFF_W9 + 1] = W9[1]; sm[OFF_W9 + 2] = B9[0]; sm[OFF_W9 + 3] = 0.0f; }
    __syncthreads();

    float* stg = sm + OFF_STAGE + warp * STG_WARP;
    const int ngroups = nrows >> 9;  // 512 rows per block-iteration (8 warps x 64)

    for (int g = blockIdx.x; g < ngroups; g += gridDim.x) {
        const int wbase = g * 512 + warp * 64;
        const int r0 = wbase + lane, r1 = wbase + lane + 32;

        ull acc0[36];
        init_pair<9>(acc0, sm + OFF_B0);

        {   // tower a -> concat[0..67], half H then half L (restage is cheap)
            ull accH[36];
            init_pair<9>(accH, sm + OFF_ba);
            tower_pass<DA, 9>(a + (size_t)wbase * DA, sm, OFF_Wa, 0, stg, lane, accH);
            feed_tower<9>(accH, 0, sm, acc0);
            ull accL[32];
            init_pair<8>(accL, sm + OFF_ba + 36);
            tower_pass<DA, 8>(a + (size_t)wbase * DA, sm, OFF_Wa, 36, stg, lane, accL);
            feed_tower<8>(accL, 36, sm, acc0);
        }
        {   // tower b -> concat[68..135]
            ull accH[36];
            init_pair<9>(accH, sm + OFF_bb);
            tower_pass<DB, 9>(b + (size_t)wbase * DB, sm, OFF_Wb, 0, stg, lane, accH);
            feed_tower<9>(accH, 68, sm, acc0);
            ull accL[32];
            init_pair<8>(accL, sm + OFF_bb + 36);
            tower_pass<DB, 8>(b + (size_t)wbase * DB, sm, OFF_Wb, 36, stg, lane, accL);
            feed_tower<8>(accL, 104, sm, acc0);
        }
        {   // meta -> concat[136..139] (no activation on meta)
            float4 mA = *reinterpret_cast<const float4*>(meta + (size_t)r0 * 4);
            float4 mB = *reinterpret_cast<const float4*>(meta + (size_t)r1 * 4);
            feed0_pair(mA.x, mB.x, 136, sm, acc0);
            feed0_pair(mA.y, mB.y, 137, sm, acc0);
            feed0_pair(mA.z, mB.z, 138, sm, acc0);
            feed0_pair(mA.w, mB.w, 139, sm, acc0);
        }

        float c1A[36], c1B[36];
#pragma unroll
        for (int p = 0; p < 9; p++) {
            float v0, v1;
            unpack2(acc0[4 * p + 0], v0, v1); c1A[4 * p + 0] = lrelu(v0); c1A[4 * p + 1] = lrelu(v1);
            unpack2(acc0[4 * p + 1], v0, v1); c1B[4 * p + 0] = lrelu(v0); c1B[4 * p + 1] = lrelu(v1);
            unpack2(acc0[4 * p + 2], v0, v1); c1A[4 * p + 2] = lrelu(v0); c1A[4 * p + 3] = lrelu(v1);
            unpack2(acc0[4 * p + 3], v0, v1); c1B[4 * p + 2] = lrelu(v0); c1B[4 * p + 3] = lrelu(v1);
        }

        float c2A[36], c2B[36]; dense_pair<34, 36>(c1A, c1B, c2A, c2B, sm, OFF_W1, OFF_B1);
        float c3A[20], c3B[20]; dense_pair<34, 20>(c2A, c2B, c3A, c3B, sm, OFF_W2, OFF_B2);
        float c4A[20], c4B[20]; dense_pair<20, 20>(c3A, c3B, c4A, c4B, sm, OFF_W3, OFF_B3);
        float c5A[20], c5B[20]; dense_pair<20, 20>(c4A, c4B, c5A, c5B, sm, OFF_W4, OFF_B4);
        float c6A[20], c6B[20]; dense_pair<20, 20>(c5A, c5B, c6A, c6B, sm, OFF_W5, OFF_B5);
        float c7A[20], c7B[20]; dense_pair<20, 20>(c6A, c6B, c7A, c7B, sm, OFF_W6, OFF_B6);
        float c8A[8],  c8B[8];  dense_pair<20, 8>(c7A, c7B, c8A, c8B, sm, OFF_W7, OFF_B7);
        float c9A[4],  c9B[4];  dense_pair<5, 4>(c8A, c8B, c9A, c9B, sm, OFF_W8, OFF_B8);

        float oA = fmaf(c9A[0], sm[OFF_W9 + 0], fmaf(c9A[1], sm[OFF_W9 + 1], sm[OFF_W9 + 2]));
        float oB = fmaf(c9B[0], sm[OFF_W9 + 0], fmaf(c9B[1], sm[OFF_W9 + 1], sm[OFF_W9 + 2]));
        outp[r0] = lrelu(oA);
        outp[r1] = lrelu(oB);
    }
}

extern "C" void kernel_launch(void* const* d_in, const int* in_sizes, int n_in,
                              void* d_out, int out_size) {
    const float* a    = (const float*)d_in[0];
    const float* b    = (const float*)d_in[1];
    const float* meta = (const float*)d_in[2];
    const float* Wa   = (const float*)d_in[3];
    const float* ba   = (const float*)d_in[4];
    const float* Wb   = (const float*)d_in[5];
    const float* bb   = (const float*)d_in[6];
    const float* W[10], *Bb[10];
    for (int i = 0; i < 10; i++) {
        W[i]  = (const float*)d_in[7 + 2 * i];
        Bb[i] = (const float*)d_in[8 + 2 * i];
    }
    float* outp = (float*)d_out;
    const int nrows = in_sizes[0] / DA;

    cudaFuncSetAttribute(Net_67954972557347_kernel,
                         cudaFuncAttributeMaxDynamicSharedMemorySize, SMEM_BYTES);

    // 143.8KB smem -> 1 block/SM; 256 threads; each block-iter covers 512 rows.
    Net_67954972557347_kernel<<<148, 256, SMEM_BYTES>>>(
        a, b, meta, Wa, ba, Wb, bb,
        W[0], Bb[0], W[1], Bb[1], W[2], Bb[2], W[3], Bb[3], W[4], Bb[4],
        W[5], Bb[5], W[6], Bb[6], W[7], Bb[7], W[8], Bb[8], W[9], Bb[9],
        outp, nrows);
}